// round 3
// baseline (speedup 1.0000x reference)
#include <cuda_runtime.h>
#include <math.h>

#define BATCH 8
#define CW    64
#define H0    256
#define W0    256
#define HP    264
#define WP    264
#define MW    32      // kept kx modes
#define MH    64      // kept ky modes (32 top + 32 bottom)
#define NL    4
#define HW    (HP*WP)            // 69696
#define NPIX  (BATCH*CW*HW)      // 35684352

// ---------------- scratch (device globals; no allocation allowed) ----------
__device__ __align__(128) float  g_h[2][NPIX];              // 2 x 142.7 MB
__device__ __align__(128) float2 g_x1[BATCH*CW*HP*MW];      // 34.6 MB
__device__ __align__(128) float2 g_x2[BATCH*CW*MH*MW];      // 8.4 MB
__device__ __align__(128) float2 g_y2[BATCH*CW*MH*MW];      // 8.4 MB
__device__ __align__(128) float2 g_y1[BATCH*CW*HP*MW];      // 34.6 MB
__device__ __align__(128) float2 g_fw[WP*MW];               // [w][kx] (cos,-sin)
__device__ __align__(128) float2 g_fh[HP*MH];               // [h][j]  (cos,-sin)
__device__ __align__(128) float2 g_gh[HP*MH];               // [h][j]  (cos,+sin)
__device__ __align__(128) float  g_aw[2*MW*WP];             // c2r inverse-W matrix [kk][w]

__device__ __forceinline__ float gelu_f(float v) {
    return 0.5f * v * (1.0f + erff(v * 0.70710678118654752f));
}

// ---------------- twiddle/matrix init (double-precision trig) --------------
__global__ void k_init() {
    int i = blockIdx.x * blockDim.x + threadIdx.x;
    if (i >= HP * MH) return;   // 16896
    const double TWO_PI = 6.283185307179586476925286766559;
    {   // g_fh / g_gh : [h][j]
        int h = i >> 6, j = i & 63;
        int ky = (j < 32) ? j : (j + (HP - MH));
        long m = ((long)h * (long)ky) % HP;
        double ang = TWO_PI * (double)m / (double)HP;
        double s, c; sincos(ang, &s, &c);
        g_fh[i] = make_float2((float)c, (float)(-s));
        g_gh[i] = make_float2((float)c, (float)( s));
    }
    if (i < WP * MW) {  // g_fw : [w][kx]
        int w = i >> 5, k = i & 31;
        long m = ((long)w * (long)k) % WP;
        double ang = TWO_PI * (double)m / (double)WP;
        double s, c; sincos(ang, &s, &c);
        g_fw[i] = make_float2((float)c, (float)(-s));
    }
    {   // g_aw : [kk][w]  kk=2k -> s*ck*cos, kk=2k+1 -> -s*ck*sin ; s = 1/(HP*WP)
        int kk = i / WP, w = i - kk * WP;
        int k = kk >> 1;
        double sc = ((k == 0) ? 1.0 : 2.0) / ((double)HP * (double)WP);
        long m = ((long)k * (long)w) % WP;
        double ang = TWO_PI * (double)m / (double)WP;
        double s, c; sincos(ang, &s, &c);
        g_aw[i] = (float)((kk & 1) ? (-sc * s) : (sc * c));
    }
}

__global__ void k_zero() {
    float4* p = (float4*)g_h[0];
    size_t n4 = (size_t)NPIX / 4;
    for (size_t i = (size_t)blockIdx.x * blockDim.x + threadIdx.x; i < n4;
         i += (size_t)gridDim.x * blockDim.x)
        p[i] = make_float4(0.f, 0.f, 0.f, 0.f);
}

// ---------------- lift: [x, gx, gy] -> gelu(W1.) -> W2. -------------------
__global__ void k_lift(const float* __restrict__ x,
                       const float* __restrict__ w1, const float* __restrict__ b1,
                       const float* __restrict__ w2, const float* __restrict__ b2) {
    __shared__ float sw1[160], sb1[32], sw2[2048], sb2[64];
    int t = threadIdx.x;
    if (t < 160) sw1[t] = w1[t];
    if (t < 32)  sb1[t] = b1[t];
    for (int i = t; i < 2048; i += 256) sw2[i] = w2[i];
    if (t < 64)  sb2[t] = b2[t];
    __syncthreads();
    int b = blockIdx.x >> 8, h = blockIdx.x & 255, w = t;
    float in5[5];
#pragma unroll
    for (int c = 0; c < 3; ++c)
        in5[c] = x[(((size_t)b * 3 + c) * H0 + h) * W0 + w];
    in5[3] = (float)h * (1.0f / 255.0f);
    in5[4] = (float)w * (1.0f / 255.0f);
    float mid[32];
#pragma unroll
    for (int o = 0; o < 32; ++o) {
        float s = sb1[o];
#pragma unroll
        for (int i = 0; i < 5; ++i) s = fmaf(sw1[o * 5 + i], in5[i], s);
        mid[o] = gelu_f(s);
    }
    float* hb = g_h[0];
#pragma unroll 4
    for (int o = 0; o < 64; ++o) {
        float s = sb2[o];
#pragma unroll
        for (int i = 0; i < 32; ++i) s = fmaf(sw2[o * 32 + i], mid[i], s);
        hb[(((size_t)b * CW + o) * HP + h) * WP + w] = s;
    }
}

// ---------------- K1: partial rDFT along W  (h -> x1) ----------------------
// x1[(b,c,h)][kx] = sum_w h[row][w] * (cos,-sin)(2pi kx w / WP)
// Both data tile AND twiddle table staged in smem; mainloop has zero LDG.
__global__ void k1_wdft(int cur) {
    extern __shared__ float s_raw[];
    float*  sA = s_raw;                                   // 64 x 264 floats
    float2* sF = reinterpret_cast<float2*>(s_raw + 64 * WP);  // [w][kx] 264x32
    const float* hb = g_h[cur] + (size_t)blockIdx.x * 64 * WP;
    {
        const float4* src = reinterpret_cast<const float4*>(hb);
        float4* dst = reinterpret_cast<float4*>(sA);
        for (int i = threadIdx.x; i < (64 * WP) / 4; i += 256) dst[i] = src[i];
        const float4* fsrc = reinterpret_cast<const float4*>(g_fw);
        float4* fdst = reinterpret_cast<float4*>(sF);
        for (int i = threadIdx.x; i < (WP * MW) / 2; i += 256) fdst[i] = fsrc[i];
    }
    __syncthreads();
    int kx = threadIdx.x & 31, rb = threadIdx.x >> 5;    // warp: 8 rows, kx 0..31
    float2 acc[8];
#pragma unroll
    for (int r = 0; r < 8; ++r) acc[r] = make_float2(0.f, 0.f);
#pragma unroll 2
    for (int w4 = 0; w4 < WP; w4 += 4) {
        float2 f0 = sF[(w4 + 0) * MW + kx];
        float2 f1 = sF[(w4 + 1) * MW + kx];
        float2 f2 = sF[(w4 + 2) * MW + kx];
        float2 f3 = sF[(w4 + 3) * MW + kx];
#pragma unroll
        for (int r = 0; r < 8; ++r) {
            float4 av = *reinterpret_cast<const float4*>(&sA[(rb + 8 * r) * WP + w4]);
            acc[r].x = fmaf(av.x, f0.x, acc[r].x);
            acc[r].y = fmaf(av.x, f0.y, acc[r].y);
            acc[r].x = fmaf(av.y, f1.x, acc[r].x);
            acc[r].y = fmaf(av.y, f1.y, acc[r].y);
            acc[r].x = fmaf(av.z, f2.x, acc[r].x);
            acc[r].y = fmaf(av.z, f2.y, acc[r].y);
            acc[r].x = fmaf(av.w, f3.x, acc[r].x);
            acc[r].y = fmaf(av.w, f3.y, acc[r].y);
        }
    }
    size_t row0 = (size_t)blockIdx.x * 64;
#pragma unroll
    for (int r = 0; r < 8; ++r)
        g_x1[(row0 + rb + 8 * r) * MW + kx] = acc[r];
}

// ---------------- K2: partial DFT along H  (x1 -> x2), complex -------------
__global__ void k2_hdft() {
    extern __shared__ float s_raw[];
    float2* sX = reinterpret_cast<float2*>(s_raw);       // [h][kx] 264x32
    int bc = blockIdx.x;
    const float4* src = reinterpret_cast<const float4*>(g_x1 + (size_t)bc * HP * MW);
    float4* dst = reinterpret_cast<float4*>(sX);
    for (int i = threadIdx.x; i < (HP * MW) / 2; i += 256) dst[i] = src[i];
    __syncthreads();
    int kx = threadIdx.x & 31, jg = threadIdx.x >> 5;    // jg: 0..7, 8 j's each
    float2 acc[8];
#pragma unroll
    for (int q = 0; q < 8; ++q) acc[q] = make_float2(0.f, 0.f);
#pragma unroll 2
    for (int h = 0; h < HP; ++h) {
        float2 xv = sX[h * MW + kx];
        const float4* f4 = reinterpret_cast<const float4*>(&g_fh[h * MH + jg * 8]);
        float4 A = __ldg(&f4[0]);
        float4 B = __ldg(&f4[1]);
        float4 C = __ldg(&f4[2]);
        float4 D = __ldg(&f4[3]);
#define CFMA2(fr, fi, q) \
        acc[q].x = fmaf((fr), xv.x, acc[q].x); acc[q].x = fmaf(-(fi), xv.y, acc[q].x); \
        acc[q].y = fmaf((fr), xv.y, acc[q].y); acc[q].y = fmaf((fi), xv.x, acc[q].y);
        CFMA2(A.x, A.y, 0) CFMA2(A.z, A.w, 1)
        CFMA2(B.x, B.y, 2) CFMA2(B.z, B.w, 3)
        CFMA2(C.x, C.y, 4) CFMA2(C.z, C.w, 5)
        CFMA2(D.x, D.y, 6) CFMA2(D.z, D.w, 7)
#undef CFMA2
    }
#pragma unroll
    for (int q = 0; q < 8; ++q)
        g_x2[((size_t)bc * MH + jg * 8 + q) * MW + kx] = acc[q];
}

// ---------------- K3: per-mode channel mixing (x2 -> y2) -------------------
__global__ void k3_mix(const float* __restrict__ spw1, const float* __restrict__ spw2, int l) {
    __shared__ float2 sX[BATCH * CW];
    int m = blockIdx.x, jj = m >> 5, kx = m & 31;
    int t = threadIdx.x;
    for (int idx = t; idx < BATCH * CW; idx += 256) {
        int b = idx >> 6, i = idx & 63;
        sX[idx] = g_x2[(((size_t)b * CW + i) * MH + jj) * MW + kx];
    }
    __syncthreads();
    const float2* wp; int jx;
    if (jj < 32) { wp = (const float2*)spw1; jx = jj; }
    else         { wp = (const float2*)spw2; jx = jj - 32; }
    size_t base = (size_t)l * 4194304 + (size_t)jx * 32 + kx;
    int o = t & 63, bp = t >> 6;                          // bp: 0..3 -> b = bp, bp+4
    float2 a0 = make_float2(0.f, 0.f), a1 = make_float2(0.f, 0.f);
#pragma unroll 4
    for (int i = 0; i < 64; ++i) {
        float2 c = __ldg(&wp[base + (size_t)(i * 64 + o) * 1024]);
        float2 xa = sX[bp * 64 + i];
        float2 xb = sX[(bp + 4) * 64 + i];
        a0.x = fmaf(xa.x, c.x, a0.x); a0.x = fmaf(-xa.y, c.y, a0.x);
        a0.y = fmaf(xa.x, c.y, a0.y); a0.y = fmaf( xa.y, c.x, a0.y);
        a1.x = fmaf(xb.x, c.x, a1.x); a1.x = fmaf(-xb.y, c.y, a1.x);
        a1.y = fmaf(xb.x, c.y, a1.y); a1.y = fmaf( xb.y, c.x, a1.y);
    }
    g_y2[(((size_t)bp      * CW + o) * MH + jj) * MW + kx] = a0;
    g_y2[(((size_t)(bp + 4)* CW + o) * MH + jj) * MW + kx] = a1;
}

// ---------------- K4: inverse DFT along H (y2 -> y1), complex, K=64 --------
__global__ void k4_invh() {
    __shared__ float2 sY[MH * MW];                       // 16 KB
    int bo = blockIdx.x;
    const float4* src = reinterpret_cast<const float4*>(g_y2 + (size_t)bo * MH * MW);
    float4* dst = reinterpret_cast<float4*>(sY);
    for (int i = threadIdx.x; i < (MH * MW) / 2; i += 256) dst[i] = src[i];
    __syncthreads();
    int kxp = threadIdx.x & 15, hg = threadIdx.x >> 4;   // kx pair, 16 h-groups
    int kx0 = kxp * 2;
    for (int k = 0; k < 17; ++k) {
        int h = k * 16 + hg;
        if (h < HP) {
            float2 a0 = make_float2(0.f, 0.f), a1 = make_float2(0.f, 0.f);
            const float4* g4 = reinterpret_cast<const float4*>(&g_gh[h * MH]);
#pragma unroll 8
            for (int j = 0; j < 64; j += 2) {
                float4 g2 = __ldg(&g4[j >> 1]);          // (c_j, s_j, c_j1, s_j1)
                float4 y0 = *reinterpret_cast<const float4*>(&sY[j * MW + kx0]);
                float4 y1v = *reinterpret_cast<const float4*>(&sY[(j + 1) * MW + kx0]);
                a0.x = fmaf(g2.x, y0.x, a0.x); a0.x = fmaf(-g2.y, y0.y, a0.x);
                a0.y = fmaf(g2.x, y0.y, a0.y); a0.y = fmaf( g2.y, y0.x, a0.y);
                a1.x = fmaf(g2.x, y0.z, a1.x); a1.x = fmaf(-g2.y, y0.w, a1.x);
                a1.y = fmaf(g2.x, y0.w, a1.y); a1.y = fmaf( g2.y, y0.z, a1.y);
                a0.x = fmaf(g2.z, y1v.x, a0.x); a0.x = fmaf(-g2.w, y1v.y, a0.x);
                a0.y = fmaf(g2.z, y1v.y, a0.y); a0.y = fmaf( g2.w, y1v.x, a0.y);
                a1.x = fmaf(g2.z, y1v.z, a1.x); a1.x = fmaf(-g2.w, y1v.w, a1.x);
                a1.y = fmaf(g2.z, y1v.w, a1.y); a1.y = fmaf( g2.w, y1v.z, a1.y);
            }
            float4 outv = make_float4(a0.x, a0.y, a1.x, a1.y);
            *reinterpret_cast<float4*>(&g_y1[((size_t)bo * HP + h) * MW + kx0]) = outv;
        }
    }
}

// ---------------- K5: conv1x1 + inverse-W(c2r) + bias + gelu ---------------
// block = (b, h); out[o][w] = sum_i cw[o][i] h[i][w] + sum_kk y1[o][kk] Aw[kk][w]
__global__ __launch_bounds__(264, 2)
void k5_combine(int cur, const float* __restrict__ cw,
                const float* __restrict__ cb, int l,
                float* __restrict__ out) {
    extern __shared__ float s_raw[];
    float* sH = s_raw;                  // 64*264 = 16896 floats
    float* sA = s_raw + 16896;          // [k][o] k<64: conv, k>=64: spectral; 128*64
    int bh = blockIdx.x;
    int b = bh / HP, h = bh - b * HP;
    bool last = (l == NL - 1);
    if (last && h >= H0) return;        // uniform per block
    int t = threadIdx.x;                // 264 threads
    const float* hb = g_h[cur];
    {
        for (int idx = t; idx < 64 * 66; idx += 264) {
            int i = idx / 66, c = idx - i * 66;
            reinterpret_cast<float4*>(sH)[i * 66 + c] =
                reinterpret_cast<const float4*>(
                    hb + (((size_t)b * CW + i) * HP + h) * WP)[c];
        }
    }
    const float* cwl = cw + (size_t)l * 4096;
    for (int r = t; r < 4096; r += 264) {
        int o = r >> 6, i = r & 63;
        sA[i * 64 + o] = cwl[r];
    }
    const float* yf = (const float*)g_y1;
    for (int r = t; r < 4096; r += 264) {
        int o = r >> 6, kk = r & 63;
        sA[(64 + kk) * 64 + o] = yf[(((size_t)b * CW + o) * HP + h) * 64 + kk];
    }
    __syncthreads();
    int mc = t & 3, wc = t >> 2;
    int obase = mc * 16, wbase = wc * 4;
    float acc[16][4];
#pragma unroll
    for (int r = 0; r < 16; ++r)
#pragma unroll
        for (int j = 0; j < 4; ++j) acc[r][j] = 0.f;
    float av[16];
#pragma unroll 4
    for (int k = 0; k < 64; ++k) {      // conv part (B from smem)
        float4 bv = *reinterpret_cast<const float4*>(&sH[k * WP + wbase]);
        *reinterpret_cast<float4*>(&av[0])  = *reinterpret_cast<const float4*>(&sA[k * 64 + obase]);
        *reinterpret_cast<float4*>(&av[4])  = *reinterpret_cast<const float4*>(&sA[k * 64 + obase + 4]);
        *reinterpret_cast<float4*>(&av[8])  = *reinterpret_cast<const float4*>(&sA[k * 64 + obase + 8]);
        *reinterpret_cast<float4*>(&av[12]) = *reinterpret_cast<const float4*>(&sA[k * 64 + obase + 12]);
#pragma unroll
        for (int r = 0; r < 16; ++r) {
            acc[r][0] = fmaf(av[r], bv.x, acc[r][0]);
            acc[r][1] = fmaf(av[r], bv.y, acc[r][1]);
            acc[r][2] = fmaf(av[r], bv.z, acc[r][2]);
            acc[r][3] = fmaf(av[r], bv.w, acc[r][3]);
        }
    }
#pragma unroll 4
    for (int k = 0; k < 64; ++k) {      // spectral part (B = g_aw from global/L1)
        float4 bv = __ldg(reinterpret_cast<const float4*>(&g_aw[k * WP + wbase]));
        *reinterpret_cast<float4*>(&av[0])  = *reinterpret_cast<const float4*>(&sA[(64 + k) * 64 + obase]);
        *reinterpret_cast<float4*>(&av[4])  = *reinterpret_cast<const float4*>(&sA[(64 + k) * 64 + obase + 4]);
        *reinterpret_cast<float4*>(&av[8])  = *reinterpret_cast<const float4*>(&sA[(64 + k) * 64 + obase + 8]);
        *reinterpret_cast<float4*>(&av[12]) = *reinterpret_cast<const float4*>(&sA[(64 + k) * 64 + obase + 12]);
#pragma unroll
        for (int r = 0; r < 16; ++r) {
            acc[r][0] = fmaf(av[r], bv.x, acc[r][0]);
            acc[r][1] = fmaf(av[r], bv.y, acc[r][1]);
            acc[r][2] = fmaf(av[r], bv.z, acc[r][2]);
            acc[r][3] = fmaf(av[r], bv.w, acc[r][3]);
        }
    }
    float* hn = g_h[cur ^ 1];
#pragma unroll
    for (int r = 0; r < 16; ++r) {
        int o = obase + r;
        float bias = __ldg(&cb[l * 64 + o]);
        float4 v = make_float4(acc[r][0] + bias, acc[r][1] + bias,
                               acc[r][2] + bias, acc[r][3] + bias);
        if (!last) {
            v.x = gelu_f(v.x); v.y = gelu_f(v.y); v.z = gelu_f(v.z); v.w = gelu_f(v.w);
            *reinterpret_cast<float4*>(
                &hn[(((size_t)b * CW + o) * HP + h) * WP + wbase]) = v;
        } else if (wbase < W0) {
            *reinterpret_cast<float4*>(
                &out[(((size_t)b * CW + o) * H0 + h) * W0 + wbase]) = v;
        }
    }
}

// ---------------- launch ---------------------------------------------------
extern "C" void kernel_launch(void* const* d_in, const int* in_sizes, int n_in,
                              void* d_out, int out_size) {
    const float* x   = (const float*)d_in[0];
    const float* lw1 = (const float*)d_in[1];
    const float* lb1 = (const float*)d_in[2];
    const float* lw2 = (const float*)d_in[3];
    const float* lb2 = (const float*)d_in[4];
    const float* cw  = (const float*)d_in[5];
    const float* cb  = (const float*)d_in[6];
    const float* sp1 = (const float*)d_in[7];
    const float* sp2 = (const float*)d_in[8];
    float* out = (float*)d_out;

    const int SMEM_K1 = 64 * WP * 4 + WP * MW * 8;    // 67584 + 67584 = 135168
    const int SMEM_K2 = HP * MW * 8;                  // 67584
    const int SMEM_K5 = (16896 + 128 * 64) * 4;       // 100352

    cudaFuncSetAttribute(k1_wdft,    cudaFuncAttributeMaxDynamicSharedMemorySize, SMEM_K1);
    cudaFuncSetAttribute(k2_hdft,    cudaFuncAttributeMaxDynamicSharedMemorySize, SMEM_K2);
    cudaFuncSetAttribute(k5_combine, cudaFuncAttributeMaxDynamicSharedMemorySize, SMEM_K5);

    k_init<<<66, 256>>>();
    k_zero<<<2048, 256>>>();
    k_lift<<<BATCH * 256, 256>>>(x, lw1, lb1, lw2, lb2);

    for (int l = 0; l < NL; ++l) {
        int cur = l & 1;
        k1_wdft<<<(BATCH * CW * HP) / 64, 256, SMEM_K1>>>(cur);
        k2_hdft<<<BATCH * CW, 256, SMEM_K2>>>();
        k3_mix<<<MH * MW, 256>>>(sp1, sp2, l);
        k4_invh<<<BATCH * CW, 256>>>();
        k5_combine<<<BATCH * HP, 264, SMEM_K5>>>(cur, cw, cb, l, out);
    }
}

// round 4
// speedup vs baseline: 1.2289x; 1.2289x over previous
#include <cuda_runtime.h>
#include <math.h>

#define BATCH 8
#define CW    64
#define H0    256
#define W0    256
#define HP    264
#define WP    264
#define MW    32      // kept kx modes
#define MH    64      // kept ky modes (32 top + 32 bottom)
#define NL    4
#define HW    (HP*WP)            // 69696
#define NPIX  (BATCH*CW*HW)      // 35684352

// ---------------- scratch (device globals; no allocation allowed) ----------
__device__ __align__(128) float  g_h[2][NPIX];              // 2 x 142.7 MB
__device__ __align__(128) float2 g_x1[BATCH*CW*HP*MW];      // 34.6 MB
__device__ __align__(128) float2 g_x2[BATCH*CW*MH*MW];      // 8.4 MB
__device__ __align__(128) float2 g_y2[BATCH*CW*MH*MW];      // 8.4 MB
__device__ __align__(128) float2 g_y1[BATCH*CW*HP*MW];      // 34.6 MB
__device__ __align__(128) float2 g_fw[WP*MW];               // [w][kx] (cos,-sin)
__device__ __align__(128) float2 g_fh[HP*MH];               // [h][j]  (cos,-sin)
__device__ __align__(128) float2 g_gh[HP*MH];               // [h][j]  (cos,+sin)
__device__ __align__(128) float  g_aw[2*MW*WP];             // c2r inverse-W matrix [kk][w]

__device__ __forceinline__ float gelu_f(float v) {
    return 0.5f * v * (1.0f + erff(v * 0.70710678118654752f));
}

// ---------------- twiddle/matrix init (double-precision trig) --------------
__global__ void k_init() {
    int i = blockIdx.x * blockDim.x + threadIdx.x;
    if (i >= HP * MH) return;   // 16896
    const double TWO_PI = 6.283185307179586476925286766559;
    {   // g_fh / g_gh : [h][j]
        int h = i >> 6, j = i & 63;
        int ky = (j < 32) ? j : (j + (HP - MH));
        long m = ((long)h * (long)ky) % HP;
        double ang = TWO_PI * (double)m / (double)HP;
        double s, c; sincos(ang, &s, &c);
        g_fh[i] = make_float2((float)c, (float)(-s));
        g_gh[i] = make_float2((float)c, (float)( s));
    }
    if (i < WP * MW) {  // g_fw : [w][kx]
        int w = i >> 5, k = i & 31;
        long m = ((long)w * (long)k) % WP;
        double ang = TWO_PI * (double)m / (double)WP;
        double s, c; sincos(ang, &s, &c);
        g_fw[i] = make_float2((float)c, (float)(-s));
    }
    {   // g_aw : [kk][w]  kk=2k -> s*ck*cos, kk=2k+1 -> -s*ck*sin ; s = 1/(HP*WP)
        int kk = i / WP, w = i - kk * WP;
        int k = kk >> 1;
        double sc = ((k == 0) ? 1.0 : 2.0) / ((double)HP * (double)WP);
        long m = ((long)k * (long)w) % WP;
        double ang = TWO_PI * (double)m / (double)WP;
        double s, c; sincos(ang, &s, &c);
        g_aw[i] = (float)((kk & 1) ? (-sc * s) : (sc * c));
    }
}

__global__ void k_zero() {
    float4* p = (float4*)g_h[0];
    size_t n4 = (size_t)NPIX / 4;
    for (size_t i = (size_t)blockIdx.x * blockDim.x + threadIdx.x; i < n4;
         i += (size_t)gridDim.x * blockDim.x)
        p[i] = make_float4(0.f, 0.f, 0.f, 0.f);
}

// ---------------- lift: [x, gx, gy] -> gelu(W1.) -> W2. -------------------
__global__ void k_lift(const float* __restrict__ x,
                       const float* __restrict__ w1, const float* __restrict__ b1,
                       const float* __restrict__ w2, const float* __restrict__ b2) {
    __shared__ float sw1[160], sb1[32], sw2[2048], sb2[64];
    int t = threadIdx.x;
    if (t < 160) sw1[t] = w1[t];
    if (t < 32)  sb1[t] = b1[t];
    for (int i = t; i < 2048; i += 256) sw2[i] = w2[i];
    if (t < 64)  sb2[t] = b2[t];
    __syncthreads();
    int b = blockIdx.x >> 8, h = blockIdx.x & 255, w = t;
    float in5[5];
#pragma unroll
    for (int c = 0; c < 3; ++c)
        in5[c] = x[(((size_t)b * 3 + c) * H0 + h) * W0 + w];
    in5[3] = (float)h * (1.0f / 255.0f);
    in5[4] = (float)w * (1.0f / 255.0f);
    float mid[32];
#pragma unroll
    for (int o = 0; o < 32; ++o) {
        float s = sb1[o];
#pragma unroll
        for (int i = 0; i < 5; ++i) s = fmaf(sw1[o * 5 + i], in5[i], s);
        mid[o] = gelu_f(s);
    }
    float* hb = g_h[0];
#pragma unroll 4
    for (int o = 0; o < 64; ++o) {
        float s = sb2[o];
#pragma unroll
        for (int i = 0; i < 32; ++i) s = fmaf(sw2[o * 32 + i], mid[i], s);
        hb[(((size_t)b * CW + o) * HP + h) * WP + w] = s;
    }
}

// ---------------- K1: partial rDFT along W  (h -> x1) ----------------------
// 32 rows per block (33 KB smem -> ~6 CTAs/SM). Twiddles from global,
// [w][kx] layout: lanes consecutive -> coalesced, table L1-resident.
__global__ __launch_bounds__(256) void k1_wdft(int cur) {
    __shared__ float sA[32 * WP];                        // 33792 B
    const float* hb = g_h[cur] + (size_t)blockIdx.x * 32 * WP;
    {
        const float4* src = reinterpret_cast<const float4*>(hb);
        float4* dst = reinterpret_cast<float4*>(sA);
        for (int i = threadIdx.x; i < (32 * WP) / 4; i += 256) dst[i] = src[i];
    }
    __syncthreads();
    int kx = threadIdx.x & 31, rb = threadIdx.x >> 5;    // warp rb: rows rb+8r
    float2 acc[4];
#pragma unroll
    for (int r = 0; r < 4; ++r) acc[r] = make_float2(0.f, 0.f);
#pragma unroll 2
    for (int w4 = 0; w4 < WP; w4 += 4) {
        float2 f0 = __ldg(&g_fw[(w4 + 0) * MW + kx]);
        float2 f1 = __ldg(&g_fw[(w4 + 1) * MW + kx]);
        float2 f2 = __ldg(&g_fw[(w4 + 2) * MW + kx]);
        float2 f3 = __ldg(&g_fw[(w4 + 3) * MW + kx]);
#pragma unroll
        for (int r = 0; r < 4; ++r) {
            float4 av = *reinterpret_cast<const float4*>(&sA[(rb + 8 * r) * WP + w4]);
            acc[r].x = fmaf(av.x, f0.x, acc[r].x);
            acc[r].y = fmaf(av.x, f0.y, acc[r].y);
            acc[r].x = fmaf(av.y, f1.x, acc[r].x);
            acc[r].y = fmaf(av.y, f1.y, acc[r].y);
            acc[r].x = fmaf(av.z, f2.x, acc[r].x);
            acc[r].y = fmaf(av.z, f2.y, acc[r].y);
            acc[r].x = fmaf(av.w, f3.x, acc[r].x);
            acc[r].y = fmaf(av.w, f3.y, acc[r].y);
        }
    }
    size_t row0 = (size_t)blockIdx.x * 32;
#pragma unroll
    for (int r = 0; r < 4; ++r)
        g_x1[(row0 + rb + 8 * r) * MW + kx] = acc[r];
}

// ---------------- K2: partial DFT along H  (x1 -> x2), complex -------------
__global__ void k2_hdft() {
    extern __shared__ float s_raw[];
    float2* sX = reinterpret_cast<float2*>(s_raw);       // [h][kx] 264x32
    int bc = blockIdx.x;
    const float4* src = reinterpret_cast<const float4*>(g_x1 + (size_t)bc * HP * MW);
    float4* dst = reinterpret_cast<float4*>(sX);
    for (int i = threadIdx.x; i < (HP * MW) / 2; i += 256) dst[i] = src[i];
    __syncthreads();
    int kx = threadIdx.x & 31, jg = threadIdx.x >> 5;    // jg: 0..7, 8 j's each
    float2 acc[8];
#pragma unroll
    for (int q = 0; q < 8; ++q) acc[q] = make_float2(0.f, 0.f);
#pragma unroll 2
    for (int h = 0; h < HP; ++h) {
        float2 xv = sX[h * MW + kx];
        const float4* f4 = reinterpret_cast<const float4*>(&g_fh[h * MH + jg * 8]);
        float4 A = __ldg(&f4[0]);
        float4 B = __ldg(&f4[1]);
        float4 C = __ldg(&f4[2]);
        float4 D = __ldg(&f4[3]);
#define CFMA2(fr, fi, q) \
        acc[q].x = fmaf((fr), xv.x, acc[q].x); acc[q].x = fmaf(-(fi), xv.y, acc[q].x); \
        acc[q].y = fmaf((fr), xv.y, acc[q].y); acc[q].y = fmaf((fi), xv.x, acc[q].y);
        CFMA2(A.x, A.y, 0) CFMA2(A.z, A.w, 1)
        CFMA2(B.x, B.y, 2) CFMA2(B.z, B.w, 3)
        CFMA2(C.x, C.y, 4) CFMA2(C.z, C.w, 5)
        CFMA2(D.x, D.y, 6) CFMA2(D.z, D.w, 7)
#undef CFMA2
    }
#pragma unroll
    for (int q = 0; q < 8; ++q)
        g_x2[((size_t)bc * MH + jg * 8 + q) * MW + kx] = acc[q];
}

// ---------------- K3: per-mode channel mixing (x2 -> y2) -------------------
// block = (jj, b-pair). lane = kx -> ALL weight loads coalesced (256B/warp).
// x tile for the 2 batches staged in smem (32 KB).
__global__ __launch_bounds__(256) void k3_mix(const float* __restrict__ spw1,
                                              const float* __restrict__ spw2, int l) {
    __shared__ float2 sX[2 * 64 * 32];                   // [b2][i][kx] 32 KB
    int jj = blockIdx.x >> 2, bp = blockIdx.x & 3;
    int b0 = bp * 2;
    int t = threadIdx.x, kx = t & 31, sub = t >> 5;      // sub 0..7 -> o = sub*8+q
    for (int idx = t; idx < 4096; idx += 256) {
        int bi = idx >> 11, rest = idx & 2047;
        int i = rest >> 5, kxl = rest & 31;
        sX[idx] = g_x2[(((size_t)(b0 + bi) * CW + i) * MH + jj) * MW + kxl];
    }
    __syncthreads();
    const float2* wp; int jx;
    if (jj < 32) { wp = (const float2*)spw1; jx = jj; }
    else         { wp = (const float2*)spw2; jx = jj - 32; }
    // float2 index of (l,i,o,jx,kx) = l*4194304 + (i*64+o)*1024 + jx*32 + kx
    size_t wbase = (size_t)l * 4194304 + (size_t)jx * 32 + kx;
    float2 a0[8], a1[8];
#pragma unroll
    for (int q = 0; q < 8; ++q) { a0[q] = make_float2(0.f, 0.f); a1[q] = make_float2(0.f, 0.f); }
#pragma unroll 2
    for (int i = 0; i < 64; ++i) {
        float2 x0 = sX[i * 32 + kx];
        float2 x1 = sX[2048 + i * 32 + kx];
        size_t row = wbase + (size_t)(i * 64 + sub * 8) * 1024;
#pragma unroll
        for (int q = 0; q < 8; ++q) {
            float2 c = __ldg(&wp[row + (size_t)q * 1024]);
            a0[q].x = fmaf(x0.x, c.x, a0[q].x); a0[q].x = fmaf(-x0.y, c.y, a0[q].x);
            a0[q].y = fmaf(x0.x, c.y, a0[q].y); a0[q].y = fmaf( x0.y, c.x, a0[q].y);
            a1[q].x = fmaf(x1.x, c.x, a1[q].x); a1[q].x = fmaf(-x1.y, c.y, a1[q].x);
            a1[q].y = fmaf(x1.x, c.y, a1[q].y); a1[q].y = fmaf( x1.y, c.x, a1[q].y);
        }
    }
#pragma unroll
    for (int q = 0; q < 8; ++q) {
        int o = sub * 8 + q;
        g_y2[(((size_t)b0       * CW + o) * MH + jj) * MW + kx] = a0[q];
        g_y2[(((size_t)(b0 + 1) * CW + o) * MH + jj) * MW + kx] = a1[q];
    }
}

// ---------------- K4: inverse DFT along H (y2 -> y1), complex, K=64 --------
__global__ void k4_invh() {
    __shared__ float2 sY[MH * MW];                       // 16 KB
    int bo = blockIdx.x;
    const float4* src = reinterpret_cast<const float4*>(g_y2 + (size_t)bo * MH * MW);
    float4* dst = reinterpret_cast<float4*>(sY);
    for (int i = threadIdx.x; i < (MH * MW) / 2; i += 256) dst[i] = src[i];
    __syncthreads();
    int kxp = threadIdx.x & 15, hg = threadIdx.x >> 4;   // kx pair, 16 h-groups
    int kx0 = kxp * 2;
    for (int k = 0; k < 17; ++k) {
        int h = k * 16 + hg;
        if (h < HP) {
            float2 a0 = make_float2(0.f, 0.f), a1 = make_float2(0.f, 0.f);
            const float4* g4 = reinterpret_cast<const float4*>(&g_gh[h * MH]);
#pragma unroll 8
            for (int j = 0; j < 64; j += 2) {
                float4 g2 = __ldg(&g4[j >> 1]);          // (c_j, s_j, c_j1, s_j1)
                float4 y0 = *reinterpret_cast<const float4*>(&sY[j * MW + kx0]);
                float4 y1v = *reinterpret_cast<const float4*>(&sY[(j + 1) * MW + kx0]);
                a0.x = fmaf(g2.x, y0.x, a0.x); a0.x = fmaf(-g2.y, y0.y, a0.x);
                a0.y = fmaf(g2.x, y0.y, a0.y); a0.y = fmaf( g2.y, y0.x, a0.y);
                a1.x = fmaf(g2.x, y0.z, a1.x); a1.x = fmaf(-g2.y, y0.w, a1.x);
                a1.y = fmaf(g2.x, y0.w, a1.y); a1.y = fmaf( g2.y, y0.z, a1.y);
                a0.x = fmaf(g2.z, y1v.x, a0.x); a0.x = fmaf(-g2.w, y1v.y, a0.x);
                a0.y = fmaf(g2.z, y1v.y, a0.y); a0.y = fmaf( g2.w, y1v.x, a0.y);
                a1.x = fmaf(g2.z, y1v.z, a1.x); a1.x = fmaf(-g2.w, y1v.w, a1.x);
                a1.y = fmaf(g2.z, y1v.w, a1.y); a1.y = fmaf( g2.w, y1v.z, a1.y);
            }
            float4 outv = make_float4(a0.x, a0.y, a1.x, a1.y);
            *reinterpret_cast<float4*>(&g_y1[((size_t)bo * HP + h) * MW + kx0]) = outv;
        }
    }
}

// ---------------- K5: conv1x1 + inverse-W(c2r) + bias + gelu ---------------
// block = (b, h); out[o][w] = sum_i cw[o][i] h[i][w] + sum_kk y1[o][kk] Aw[kk][w]
__global__ __launch_bounds__(264, 2)
void k5_combine(int cur, const float* __restrict__ cw,
                const float* __restrict__ cb, int l,
                float* __restrict__ out) {
    extern __shared__ float s_raw[];
    float* sH = s_raw;                  // 64*264 = 16896 floats
    float* sA = s_raw + 16896;          // [k][o] k<64: conv, k>=64: spectral; 128*64
    int bh = blockIdx.x;
    int b = bh / HP, h = bh - b * HP;
    bool last = (l == NL - 1);
    if (last && h >= H0) return;        // uniform per block
    int t = threadIdx.x;                // 264 threads
    const float* hb = g_h[cur];
    {
        for (int idx = t; idx < 64 * 66; idx += 264) {
            int i = idx / 66, c = idx - i * 66;
            reinterpret_cast<float4*>(sH)[i * 66 + c] =
                reinterpret_cast<const float4*>(
                    hb + (((size_t)b * CW + i) * HP + h) * WP)[c];
        }
    }
    const float* cwl = cw + (size_t)l * 4096;
    for (int r = t; r < 4096; r += 264) {
        int o = r >> 6, i = r & 63;
        sA[i * 64 + o] = cwl[r];
    }
    const float* yf = (const float*)g_y1;
    for (int r = t; r < 4096; r += 264) {
        int o = r >> 6, kk = r & 63;
        sA[(64 + kk) * 64 + o] = yf[(((size_t)b * CW + o) * HP + h) * 64 + kk];
    }
    __syncthreads();
    int mc = t & 3, wc = t >> 2;
    int obase = mc * 16, wbase = wc * 4;
    float acc[16][4];
#pragma unroll
    for (int r = 0; r < 16; ++r)
#pragma unroll
        for (int j = 0; j < 4; ++j) acc[r][j] = 0.f;
    float av[16];
#pragma unroll 4
    for (int k = 0; k < 64; ++k) {      // conv part (B from smem)
        float4 bv = *reinterpret_cast<const float4*>(&sH[k * WP + wbase]);
        *reinterpret_cast<float4*>(&av[0])  = *reinterpret_cast<const float4*>(&sA[k * 64 + obase]);
        *reinterpret_cast<float4*>(&av[4])  = *reinterpret_cast<const float4*>(&sA[k * 64 + obase + 4]);
        *reinterpret_cast<float4*>(&av[8])  = *reinterpret_cast<const float4*>(&sA[k * 64 + obase + 8]);
        *reinterpret_cast<float4*>(&av[12]) = *reinterpret_cast<const float4*>(&sA[k * 64 + obase + 12]);
#pragma unroll
        for (int r = 0; r < 16; ++r) {
            acc[r][0] = fmaf(av[r], bv.x, acc[r][0]);
            acc[r][1] = fmaf(av[r], bv.y, acc[r][1]);
            acc[r][2] = fmaf(av[r], bv.z, acc[r][2]);
            acc[r][3] = fmaf(av[r], bv.w, acc[r][3]);
        }
    }
#pragma unroll 4
    for (int k = 0; k < 64; ++k) {      // spectral part (B = g_aw from global/L1)
        float4 bv = __ldg(reinterpret_cast<const float4*>(&g_aw[k * WP + wbase]));
        *reinterpret_cast<float4*>(&av[0])  = *reinterpret_cast<const float4*>(&sA[(64 + k) * 64 + obase]);
        *reinterpret_cast<float4*>(&av[4])  = *reinterpret_cast<const float4*>(&sA[(64 + k) * 64 + obase + 4]);
        *reinterpret_cast<float4*>(&av[8])  = *reinterpret_cast<const float4*>(&sA[(64 + k) * 64 + obase + 8]);
        *reinterpret_cast<float4*>(&av[12]) = *reinterpret_cast<const float4*>(&sA[(64 + k) * 64 + obase + 12]);
#pragma unroll
        for (int r = 0; r < 16; ++r) {
            acc[r][0] = fmaf(av[r], bv.x, acc[r][0]);
            acc[r][1] = fmaf(av[r], bv.y, acc[r][1]);
            acc[r][2] = fmaf(av[r], bv.z, acc[r][2]);
            acc[r][3] = fmaf(av[r], bv.w, acc[r][3]);
        }
    }
    float* hn = g_h[cur ^ 1];
#pragma unroll
    for (int r = 0; r < 16; ++r) {
        int o = obase + r;
        float bias = __ldg(&cb[l * 64 + o]);
        float4 v = make_float4(acc[r][0] + bias, acc[r][1] + bias,
                               acc[r][2] + bias, acc[r][3] + bias);
        if (!last) {
            v.x = gelu_f(v.x); v.y = gelu_f(v.y); v.z = gelu_f(v.z); v.w = gelu_f(v.w);
            *reinterpret_cast<float4*>(
                &hn[(((size_t)b * CW + o) * HP + h) * WP + wbase]) = v;
        } else if (wbase < W0) {
            *reinterpret_cast<float4*>(
                &out[(((size_t)b * CW + o) * H0 + h) * W0 + wbase]) = v;
        }
    }
}

// ---------------- launch ---------------------------------------------------
extern "C" void kernel_launch(void* const* d_in, const int* in_sizes, int n_in,
                              void* d_out, int out_size) {
    const float* x   = (const float*)d_in[0];
    const float* lw1 = (const float*)d_in[1];
    const float* lb1 = (const float*)d_in[2];
    const float* lw2 = (const float*)d_in[3];
    const float* lb2 = (const float*)d_in[4];
    const float* cw  = (const float*)d_in[5];
    const float* cb  = (const float*)d_in[6];
    const float* sp1 = (const float*)d_in[7];
    const float* sp2 = (const float*)d_in[8];
    float* out = (float*)d_out;

    const int SMEM_K2 = HP * MW * 8;                  // 67584
    const int SMEM_K5 = (16896 + 128 * 64) * 4;       // 100352

    cudaFuncSetAttribute(k2_hdft,    cudaFuncAttributeMaxDynamicSharedMemorySize, SMEM_K2);
    cudaFuncSetAttribute(k5_combine, cudaFuncAttributeMaxDynamicSharedMemorySize, SMEM_K5);

    k_init<<<66, 256>>>();
    k_zero<<<2048, 256>>>();
    k_lift<<<BATCH * 256, 256>>>(x, lw1, lb1, lw2, lb2);

    for (int l = 0; l < NL; ++l) {
        int cur = l & 1;
        k1_wdft<<<(BATCH * CW * HP) / 32, 256>>>(cur);
        k2_hdft<<<BATCH * CW, 256, SMEM_K2>>>();
        k3_mix<<<MH * 4, 256>>>(sp1, sp2, l);
        k4_invh<<<BATCH * CW, 256>>>();
        k5_combine<<<BATCH * HP, 264, SMEM_K5>>>(cur, cw, cb, l, out);
    }
}